// round 1
// baseline (speedup 1.0000x reference)
#include <cuda_runtime.h>

#define N_R 40000
#define N_U 30000
#define N_P 30000
#define NN  100000
#define EE  1600000
#define F   128
#define C   40

// ---------------- device scratch (static, no allocation) ----------------
__device__ float g_h1[(size_t)NN * F];   // projected features (layer-1 GEMM output, fused)
__device__ float g_h [(size_t)NN * F];   // relu(aggregate of h1)
__device__ float g_h2[(size_t)NN * C];   // h @ W2
__device__ int   g_deg[NN];
__device__ int   g_rowptr[NN + 1];
__device__ int   g_cursor[NN];
__device__ int   g_srcs[EE];
__device__ float g_Wf[(5 + 7 + 6) * F];  // fused W_seg @ W1 (rows 0-4:r, 5-11:u, 12-17:p)
__device__ float g_bf[3 * F];            // fused b_seg @ W1

// ---------------- weight fusion: Wf = W_seg @ W1, bf = b_seg @ W1 ----------------
__global__ void k_fuse(const float* __restrict__ Wr, const float* __restrict__ br,
                       const float* __restrict__ Wu, const float* __restrict__ bu,
                       const float* __restrict__ Wp, const float* __restrict__ bp,
                       const float* __restrict__ W1)
{
    int row = blockIdx.x;      // 0..20
    int f   = threadIdx.x;     // 0..127
    float acc = 0.f;
    if (row < 5) {
        for (int j = 0; j < F; j++) acc += Wr[row * F + j] * W1[j * F + f];
        g_Wf[row * F + f] = acc;
    } else if (row < 12) {
        int r = row - 5;
        for (int j = 0; j < F; j++) acc += Wu[r * F + j] * W1[j * F + f];
        g_Wf[row * F + f] = acc;
    } else if (row < 18) {
        int r = row - 12;
        for (int j = 0; j < F; j++) acc += Wp[r * F + j] * W1[j * F + f];
        g_Wf[row * F + f] = acc;
    } else {
        const float* b = (row == 18) ? br : (row == 19) ? bu : bp;
        for (int j = 0; j < F; j++) acc += b[j] * W1[j * F + f];
        g_bf[(row - 18) * F + f] = acc;
    }
}

// ---------------- h1 = in_seg @ Wf + bf  (one thread per output element) ----------------
__global__ void k_proj(const float* __restrict__ xr, const float* __restrict__ xu,
                       const float* __restrict__ xp)
{
    int idx = blockIdx.x * blockDim.x + threadIdx.x;
    if (idx >= NN * F) return;
    int node = idx >> 7;
    int f    = idx & (F - 1);
    float acc;
    if (node < N_R) {
        acc = g_bf[f];
        const float* in = xr + (size_t)node * 5;
        #pragma unroll
        for (int k = 0; k < 5; k++) acc += in[k] * g_Wf[k * F + f];
    } else if (node < N_R + N_U) {
        acc = g_bf[F + f];
        const float* in = xu + (size_t)(node - N_R) * 7;
        #pragma unroll
        for (int k = 0; k < 7; k++) acc += in[k] * g_Wf[(5 + k) * F + f];
    } else {
        acc = g_bf[2 * F + f];
        const float* in = xp + (size_t)(node - N_R - N_U) * 6;
        #pragma unroll
        for (int k = 0; k < 6; k++) acc += in[k] * g_Wf[(12 + k) * F + f];
    }
    g_h1[idx] = acc;
}

// ---------------- CSR build ----------------
__global__ void k_zero_deg()
{
    int i = blockIdx.x * blockDim.x + threadIdx.x;
    if (i < NN) g_deg[i] = 0;
}

__global__ void k_hist(const int* __restrict__ dst)
{
    int e = blockIdx.x * blockDim.x + threadIdx.x;
    if (e < EE) atomicAdd(&g_deg[dst[e]], 1);
}

// single-block hierarchical exclusive scan of g_deg -> g_rowptr / g_cursor
__global__ void k_scan()
{
    const int T = 1024, VT = 4, CHUNK = T * VT;   // 4096 per chunk, 25 chunks
    __shared__ int wsum[32];
    __shared__ int s_total;
    __shared__ int s_carry;
    if (threadIdx.x == 0) s_carry = 0;
    __syncthreads();
    int lane = threadIdx.x & 31, wid = threadIdx.x >> 5;

    for (int base = 0; base < NN; base += CHUNK) {
        int v[VT];
        int tsum = 0;
        int i0 = base + threadIdx.x * VT;
        #pragma unroll
        for (int k = 0; k < VT; k++) {
            int i = i0 + k;
            v[k] = (i < NN) ? g_deg[i] : 0;
            tsum += v[k];
        }
        // warp inclusive scan of per-thread sums
        int incl = tsum;
        #pragma unroll
        for (int off = 1; off < 32; off <<= 1) {
            int t = __shfl_up_sync(0xffffffffu, incl, off);
            if (lane >= off) incl += t;
        }
        if (lane == 31) wsum[wid] = incl;
        __syncthreads();
        if (wid == 0) {
            int w  = wsum[lane];
            int wi = w;
            #pragma unroll
            for (int off = 1; off < 32; off <<= 1) {
                int t = __shfl_up_sync(0xffffffffu, wi, off);
                if (lane >= off) wi += t;
            }
            wsum[lane] = wi - w;           // exclusive warp prefix
            if (lane == 31) s_total = wi;  // chunk total
        }
        __syncthreads();
        int texcl = s_carry + wsum[wid] + (incl - tsum);
        int run = 0;
        #pragma unroll
        for (int k = 0; k < VT; k++) {
            int i = i0 + k;
            if (i < NN) {
                g_rowptr[i] = texcl + run;
                g_cursor[i] = texcl + run;
            }
            run += v[k];
        }
        __syncthreads();
        if (threadIdx.x == 0) s_carry += s_total;
        __syncthreads();
    }
    if (threadIdx.x == 0) g_rowptr[NN] = s_carry;
}

__global__ void k_scatter(const int* __restrict__ src, const int* __restrict__ dst)
{
    int e = blockIdx.x * blockDim.x + threadIdx.x;
    if (e < EE) {
        int d = dst[e];
        int p = atomicAdd(&g_cursor[d], 1);
        g_srcs[p] = src[e];
    }
}

// ---------------- layer-1 aggregate + relu : warp per node, float4 per lane ----------------
__global__ void k_agg1()
{
    int gw = (blockIdx.x * blockDim.x + threadIdx.x) >> 5;
    if (gw >= NN) return;
    int lane = threadIdx.x & 31;
    int b = g_rowptr[gw], e = g_rowptr[gw + 1];
    float4 acc = make_float4(0.f, 0.f, 0.f, 0.f);
    int j = b;
    for (; j + 1 < e; j += 2) {
        int s0 = g_srcs[j];
        int s1 = g_srcs[j + 1];
        float4 r0 = ((const float4*)(g_h1 + (size_t)s0 * F))[lane];
        float4 r1 = ((const float4*)(g_h1 + (size_t)s1 * F))[lane];
        acc.x += r0.x + r1.x;
        acc.y += r0.y + r1.y;
        acc.z += r0.z + r1.z;
        acc.w += r0.w + r1.w;
    }
    if (j < e) {
        int s0 = g_srcs[j];
        float4 r0 = ((const float4*)(g_h1 + (size_t)s0 * F))[lane];
        acc.x += r0.x; acc.y += r0.y; acc.z += r0.z; acc.w += r0.w;
    }
    acc.x = fmaxf(acc.x, 0.f);
    acc.y = fmaxf(acc.y, 0.f);
    acc.z = fmaxf(acc.z, 0.f);
    acc.w = fmaxf(acc.w, 0.f);
    ((float4*)(g_h + (size_t)gw * F))[lane] = acc;
}

// ---------------- h2 = h @ W2 : 8 nodes per block, 320 threads ----------------
__global__ void k_gemm2(const float* __restrict__ W2)
{
    __shared__ float W2s[F * C];     // 20 KB
    __shared__ float hs[8 * F];      // 4 KB
    for (int i = threadIdx.x; i < F * C; i += blockDim.x) W2s[i] = W2[i];
    int node0 = blockIdx.x * 8;
    for (int i = threadIdx.x; i < 8 * F; i += blockDim.x) {
        int n = node0 + (i >> 7);
        hs[i] = (n < NN) ? g_h[(size_t)n * F + (i & (F - 1))] : 0.f;
    }
    __syncthreads();
    int ln = threadIdx.x / C;    // 0..7
    int c  = threadIdx.x % C;
    int node = node0 + ln;
    if (node < NN) {
        float acc = 0.f;
        const float* hrow = hs + ln * F;
        #pragma unroll 8
        for (int k = 0; k < F; k++) acc += hrow[k] * W2s[k * C + c];
        g_h2[(size_t)node * C + c] = acc;
    }
}

// ---------------- layer-2 aggregate : warp per node (lanes cover 40 feats) ----------------
__global__ void k_agg2(float* __restrict__ out)
{
    int gw = (blockIdx.x * blockDim.x + threadIdx.x) >> 5;
    if (gw >= NN) return;
    int lane = threadIdx.x & 31;
    int b = g_rowptr[gw], e = g_rowptr[gw + 1];
    float a0 = 0.f, a1 = 0.f;
    for (int j = b; j < e; j++) {
        int s = g_srcs[j];
        const float* r = g_h2 + (size_t)s * C;
        a0 += r[lane];
        if (lane < C - 32) a1 += r[32 + lane];
    }
    out[(size_t)gw * C + lane] = a0;
    if (lane < C - 32) out[(size_t)gw * C + 32 + lane] = a1;
}

// ---------------- launch ----------------
extern "C" void kernel_launch(void* const* d_in, const int* in_sizes, int n_in,
                              void* d_out, int out_size)
{
    const float* xr = (const float*)d_in[0];
    const float* xu = (const float*)d_in[1];
    const float* xp = (const float*)d_in[2];
    const int*   ei = (const int*)  d_in[3];   // [2, E] int32
    const float* Wr = (const float*)d_in[4];
    const float* br = (const float*)d_in[5];
    const float* Wu = (const float*)d_in[6];
    const float* bu = (const float*)d_in[7];
    const float* Wp = (const float*)d_in[8];
    const float* bp = (const float*)d_in[9];
    const float* W1 = (const float*)d_in[10];
    const float* W2 = (const float*)d_in[11];
    float* out = (float*)d_out;

    const int* src = ei;
    const int* dst = ei + EE;

    k_fuse<<<21, 128>>>(Wr, br, Wu, bu, Wp, bp, W1);
    k_proj<<<(NN * F + 255) / 256, 256>>>(xr, xu, xp);
    k_zero_deg<<<(NN + 255) / 256, 256>>>();
    k_hist<<<(EE + 255) / 256, 256>>>(dst);
    k_scan<<<1, 1024>>>();
    k_scatter<<<(EE + 255) / 256, 256>>>(src, dst);
    k_agg1<<<(NN * 32 + 255) / 256, 256>>>();
    k_gemm2<<<(NN + 7) / 8, 320>>>(W2);
    k_agg2<<<(NN * 32 + 255) / 256, 256>>>(out);
}

// round 2
// speedup vs baseline: 2.0223x; 2.0223x over previous
#include <cuda_runtime.h>

#define N_R 40000
#define N_U 30000
#define N_P 30000
#define NN  100000
#define EE  1600000
#define F   128
#define C   40
#define ZC  21            // stacked input width: 5 + 7 + 6 + 3 bias-count cols

// ---------------- device scratch (static, no allocation) ----------------
__device__ float g_z [(size_t)(NN + 64) * ZC];  // aggregated raw features (padded)
__device__ float g_h2[(size_t)NN * C];          // relu(z@Ws) @ W2
__device__ float g_Ws[ZC * F];                  // stacked fused weights
__device__ int   g_deg[NN];
__device__ int   g_rowptr[NN + 1];
__device__ int   g_cursor[NN];
__device__ int   g_srcs[EE];
__device__ int   g_blocksum[128];
__device__ int   g_blockoff[128];

// ---------------- weight fusion: Ws rows 0-4 = Wr@W1, 5-11 = Wu@W1, 12-17 = Wp@W1,
//                                 18 = br@W1, 19 = bu@W1, 20 = bp@W1
__global__ void k_fuse(const float* __restrict__ Wr, const float* __restrict__ br,
                       const float* __restrict__ Wu, const float* __restrict__ bu,
                       const float* __restrict__ Wp, const float* __restrict__ bp,
                       const float* __restrict__ W1)
{
    int row = blockIdx.x;      // 0..20
    int f   = threadIdx.x;     // 0..127
    const float* v;
    if (row < 5)        v = Wr + row * F;
    else if (row < 12)  v = Wu + (row - 5) * F;
    else if (row < 18)  v = Wp + (row - 12) * F;
    else if (row == 18) v = br;
    else if (row == 19) v = bu;
    else                v = bp;
    float acc = 0.f;
    for (int j = 0; j < F; j++) acc += v[j] * W1[j * F + f];
    g_Ws[row * F + f] = acc;
}

// ---------------- CSR build ----------------
__global__ void k_zero_deg()
{
    int i = blockIdx.x * blockDim.x + threadIdx.x;
    if (i < NN) g_deg[i] = 0;
}

__global__ void k_hist(const int* __restrict__ dst)
{
    int e = blockIdx.x * blockDim.x + threadIdx.x;
    if (e < EE) atomicAdd(&g_deg[dst[e]], 1);
}

// parallel scan, stage 1: per-block (1024 items) exclusive scan + block sums
__global__ void k_scan1()
{
    __shared__ int wsum[8];
    int t = threadIdx.x;               // 0..255
    int lane = t & 31, wid = t >> 5;
    int i0 = blockIdx.x * 1024 + t * 4;
    int v[4], tsum = 0;
    #pragma unroll
    for (int k = 0; k < 4; k++) {
        v[k] = (i0 + k < NN) ? g_deg[i0 + k] : 0;
        tsum += v[k];
    }
    int incl = tsum;
    #pragma unroll
    for (int off = 1; off < 32; off <<= 1) {
        int x = __shfl_up_sync(0xffffffffu, incl, off);
        if (lane >= off) incl += x;
    }
    if (lane == 31) wsum[wid] = incl;
    __syncthreads();
    if (t < 8) {
        int w = wsum[t], wi = w;
        #pragma unroll
        for (int off = 1; off < 8; off <<= 1) {
            int x = __shfl_up_sync(0xffu, wi, off);
            if (t >= off) wi += x;
        }
        wsum[t] = wi - w;
        if (t == 7) g_blocksum[blockIdx.x] = wi;
    }
    __syncthreads();
    int excl = wsum[wid] + (incl - tsum);
    int run = 0;
    #pragma unroll
    for (int k = 0; k < 4; k++) {
        if (i0 + k < NN) g_rowptr[i0 + k] = excl + run;
        run += v[k];
    }
}

// stage 2: scan the (<=128) block sums
__global__ void k_scan2(int nblocks)
{
    __shared__ int ws[4];
    int t = threadIdx.x;               // 0..127
    int lane = t & 31, wid = t >> 5;
    int v = (t < nblocks) ? g_blocksum[t] : 0;
    int incl = v;
    #pragma unroll
    for (int off = 1; off < 32; off <<= 1) {
        int x = __shfl_up_sync(0xffffffffu, incl, off);
        if (lane >= off) incl += x;
    }
    if (lane == 31) ws[wid] = incl;
    __syncthreads();
    if (t == 0) {
        int a = 0;
        #pragma unroll
        for (int i = 0; i < 4; i++) { int x = ws[i]; ws[i] = a; a += x; }
    }
    __syncthreads();
    if (t < nblocks) g_blockoff[t] = ws[wid] + incl - v;
}

// stage 3: add block offsets, init cursor
__global__ void k_scan3()
{
    int i = blockIdx.x * blockDim.x + threadIdx.x;
    if (i < NN) {
        int r = g_rowptr[i] + g_blockoff[i >> 10];
        g_rowptr[i] = r;
        g_cursor[i] = r;
    }
    if (i == 0) g_rowptr[NN] = EE;
}

__global__ void k_scatter(const int* __restrict__ src, const int* __restrict__ dst)
{
    int e = blockIdx.x * blockDim.x + threadIdx.x;
    if (e < EE) {
        int d = dst[e];
        int p = atomicAdd(&g_cursor[d], 1);
        g_srcs[p] = src[e];
    }
}

// ---------------- layer-1 raw aggregate: z[dst] = sum of src raw features (by segment)
// 8 lanes per node; lane = feature index, 3 segment accumulators per lane
__global__ void k_aggz(const float* __restrict__ xr, const float* __restrict__ xu,
                       const float* __restrict__ xp)
{
    int gid  = blockIdx.x * blockDim.x + threadIdx.x;
    int node = gid >> 3;
    if (node >= NN) return;
    int lane = gid & 7;
    int b = g_rowptr[node], e = g_rowptr[node + 1];
    float aR = 0.f, aU = 0.f, aP = 0.f;
    int   cR = 0,   cU = 0,   cP = 0;
    for (int j = b; j < e; j++) {
        int s = g_srcs[j];
        if (s < N_R) {
            if (lane < 5) aR += xr[s * 5 + lane];
            cR++;
        } else if (s < N_R + N_U) {
            if (lane < 7) aU += xu[(s - N_R) * 7 + lane];
            cU++;
        } else {
            if (lane < 6) aP += xp[(s - N_R - N_U) * 6 + lane];
            cP++;
        }
    }
    float* zr = g_z + (size_t)node * ZC;
    if (lane < 5) zr[lane]      = aR;
    if (lane < 7) zr[5 + lane]  = aU;
    if (lane < 6) zr[12 + lane] = aP;
    if (lane == 7) {
        zr[18] = (float)cR;
        zr[19] = (float)cU;
        zr[20] = (float)cP;
    }
}

// ---------------- fused MLP: h2 = relu(z @ Ws) @ W2, 64 nodes per block
#define TN   64
#define HPAD 132   // padded h row stride (bank-conflict free in phase B)
__global__ void k_mlp(const float* __restrict__ W2)
{
    extern __shared__ float sm[];
    float* Wss = sm;                  // 21*128 = 2688
    float* W2s = Wss + ZC * F;        // 128*40 = 5120
    float* zsm = W2s + F * C;         // 64*21  = 1344
    float* hsm = zsm + TN * ZC;       // 64*132 = 8448

    int tid = threadIdx.x;            // 0..255
    for (int i = tid; i < ZC * F; i += 256) Wss[i] = g_Ws[i];
    for (int i = tid; i < F * C;  i += 256) W2s[i] = W2[i];

    int nodeBase = blockIdx.x * TN;
    // z rows are contiguous: copy 64*21 floats straight
    const float* zg = g_z + (size_t)nodeBase * ZC;
    for (int i = tid; i < TN * ZC; i += 256) zsm[i] = zg[i];
    __syncthreads();

    // ---- phase A: h = relu(z @ Ws); thread = 4 nodes x 8 cols
    {
        int ng = tid >> 4;            // 0..15 -> nodes ng*4..+3
        int cl = tid & 15;            // cols cl + 16*i
        int n0 = ng * 4;
        float acc[4][8];
        #pragma unroll
        for (int j = 0; j < 4; j++)
            #pragma unroll
            for (int i = 0; i < 8; i++) acc[j][i] = 0.f;
        #pragma unroll
        for (int k = 0; k < ZC; k++) {
            float z0 = zsm[(n0 + 0) * ZC + k];
            float z1 = zsm[(n0 + 1) * ZC + k];
            float z2 = zsm[(n0 + 2) * ZC + k];
            float z3 = zsm[(n0 + 3) * ZC + k];
            #pragma unroll
            for (int i = 0; i < 8; i++) {
                float w = Wss[k * F + cl + 16 * i];
                acc[0][i] += z0 * w;
                acc[1][i] += z1 * w;
                acc[2][i] += z2 * w;
                acc[3][i] += z3 * w;
            }
        }
        #pragma unroll
        for (int j = 0; j < 4; j++)
            #pragma unroll
            for (int i = 0; i < 8; i++)
                hsm[(n0 + j) * HPAD + cl + 16 * i] = fmaxf(acc[j][i], 0.f);
    }
    __syncthreads();

    // ---- phase B: h2 = h @ W2; thread = 2 nodes x 5 cols
    {
        int ng = tid >> 3;            // 0..31 -> nodes ng*2, ng*2+1
        int cl = tid & 7;             // cols cl + 8*i, i<5
        int n0 = ng * 2;
        float a0[5], a1[5];
        #pragma unroll
        for (int i = 0; i < 5; i++) { a0[i] = 0.f; a1[i] = 0.f; }
        #pragma unroll 4
        for (int c = 0; c < F; c++) {
            float h0 = hsm[n0 * HPAD + c];
            float h1 = hsm[(n0 + 1) * HPAD + c];
            #pragma unroll
            for (int i = 0; i < 5; i++) {
                float w = W2s[c * C + cl + 8 * i];
                a0[i] += h0 * w;
                a1[i] += h1 * w;
            }
        }
        int gn0 = nodeBase + n0;
        if (gn0 < NN) {
            #pragma unroll
            for (int i = 0; i < 5; i++) g_h2[(size_t)gn0 * C + cl + 8 * i] = a0[i];
        }
        if (gn0 + 1 < NN) {
            #pragma unroll
            for (int i = 0; i < 5; i++) g_h2[(size_t)(gn0 + 1) * C + cl + 8 * i] = a1[i];
        }
    }
}

// ---------------- layer-2 aggregate: warp per node, 40 output cols
__global__ void k_agg2(float* __restrict__ out)
{
    int gw = (blockIdx.x * blockDim.x + threadIdx.x) >> 5;
    if (gw >= NN) return;
    int lane = threadIdx.x & 31;
    int b = g_rowptr[gw], e = g_rowptr[gw + 1];
    float a0 = 0.f, a1 = 0.f;
    int j = b;
    for (; j + 1 < e; j += 2) {
        int s0 = g_srcs[j], s1 = g_srcs[j + 1];
        const float* r0 = g_h2 + (size_t)s0 * C;
        const float* r1 = g_h2 + (size_t)s1 * C;
        a0 += r0[lane] + r1[lane];
        if (lane < C - 32) a1 += r0[32 + lane] + r1[32 + lane];
    }
    if (j < e) {
        int s0 = g_srcs[j];
        const float* r0 = g_h2 + (size_t)s0 * C;
        a0 += r0[lane];
        if (lane < C - 32) a1 += r0[32 + lane];
    }
    out[(size_t)gw * C + lane] = a0;
    if (lane < C - 32) out[(size_t)gw * C + 32 + lane] = a1;
}

// ---------------- launch ----------------
extern "C" void kernel_launch(void* const* d_in, const int* in_sizes, int n_in,
                              void* d_out, int out_size)
{
    const float* xr = (const float*)d_in[0];
    const float* xu = (const float*)d_in[1];
    const float* xp = (const float*)d_in[2];
    const int*   ei = (const int*)  d_in[3];
    const float* Wr = (const float*)d_in[4];
    const float* br = (const float*)d_in[5];
    const float* Wu = (const float*)d_in[6];
    const float* bu = (const float*)d_in[7];
    const float* Wp = (const float*)d_in[8];
    const float* bp = (const float*)d_in[9];
    const float* W1 = (const float*)d_in[10];
    const float* W2 = (const float*)d_in[11];
    float* out = (float*)d_out;

    const int* src = ei;
    const int* dst = ei + EE;

    const int smem_mlp = (ZC * F + F * C + TN * ZC + TN * HPAD) * sizeof(float);
    static int attr_set = 0;
    cudaFuncSetAttribute(k_mlp, cudaFuncAttributeMaxDynamicSharedMemorySize, smem_mlp);
    (void)attr_set;

    const int nScanBlocks = (NN + 1023) / 1024;   // 98

    k_fuse<<<ZC, 128>>>(Wr, br, Wu, bu, Wp, bp, W1);
    k_zero_deg<<<(NN + 255) / 256, 256>>>();
    k_hist<<<(EE + 255) / 256, 256>>>(dst);
    k_scan1<<<nScanBlocks, 256>>>();
    k_scan2<<<1, 128>>>(nScanBlocks);
    k_scan3<<<(NN + 255) / 256, 256>>>();
    k_scatter<<<(EE + 255) / 256, 256>>>(src, dst);
    k_aggz<<<(NN * 8 + 255) / 256, 256>>>(xr, xu, xp);
    k_mlp<<<(NN + TN - 1) / TN, 256, smem_mlp>>>(W2);
    k_agg2<<<(NN * 32 + 255) / 256, 256>>>(out);
}